// round 14
// baseline (speedup 1.0000x reference)
#include <cuda_runtime.h>
#include <cuda_fp16.h>
#include <cstdint>
#include <cfloat>
#include <math.h>

// ---------------- problem constants ----------------
#define NROWS   8192          // B*S
#define CDIM    2048
#define VDIM    50257
#define VT      128           // v-tile width (CTA N)
#define NVT     393           // ceil(VDIM/128)
#define KC      64            // K elems per chunk (128B f16 rows)
#define NKC     (CDIM / KC)   // 32 chunks per v-tile
#define MB      128           // rows per CTA (M)
#define NMB     (NROWS / MB)  // 64
#define TPS     3             // v-tiles per split; 131*3 = 393 exactly
#define NSPLIT  131
#define GRID_MAIN (NSPLIT * NMB)   // 8384
#define LOG2E   1.4426950408889634f

// ---------------- smem layout ----------------
#define STAGES     3
#define STAGE_SZ   32768      // A 128x128B (16KB) + B 128x128B (16KB)
#define SM_LABELS  0          // 128 ints
#define SM_ROWSUM  512        // 128 floats
#define SM_STAGE   1024
#define SMEM_TOTAL (SM_STAGE + STAGES * STAGE_SZ)   // 99328 -> 2 CTAs/SM

// ---------------- device scratch ----------------
__device__ uint4 g_xh[(size_t)NROWS * CDIM / 8];   // x as f16
__device__ uint4 g_wh[(size_t)VDIM * CDIM / 8];    // W as f16
__device__ float g_psum[(size_t)NVT * NROWS];      // per-(vtile,row) partials
__device__ float g_lab[NROWS];
__device__ int   g_labels[NROWS];

// ---------------- helpers ----------------
__device__ __forceinline__ uint32_t s2u(const void* p) {
    uint32_t a;
    asm("{ .reg .u64 t; cvta.to.shared.u64 t, %1; cvt.u32.u64 %0, t; }" : "=r"(a) : "l"(p));
    return a;
}
__device__ __forceinline__ float ex2f(float x) {
    float y; asm("ex2.approx.ftz.f32 %0, %1;" : "=f"(y) : "f"(x)); return y;
}
__device__ __forceinline__ void cpa16(uint32_t dst, const void* src) {
    asm volatile("cp.async.cg.shared.global [%0], [%1], 16;" :: "r"(dst), "l"(src) : "memory");
}
__device__ __forceinline__ void cp_commit() {
    asm volatile("cp.async.commit_group;" ::: "memory");
}
template <int N>
__device__ __forceinline__ void cp_wait() {
    asm volatile("cp.async.wait_group %0;" :: "n"(N) : "memory");
}
__device__ __forceinline__ uint32_t sw128(uint32_t off) { return off ^ ((off >> 3) & 0x70); }

__device__ __forceinline__ void ldsm4(uint32_t& r0, uint32_t& r1, uint32_t& r2, uint32_t& r3,
                                      uint32_t addr) {
    asm volatile("ldmatrix.sync.aligned.m8n8.x4.shared.b16 {%0,%1,%2,%3}, [%4];"
                 : "=r"(r0), "=r"(r1), "=r"(r2), "=r"(r3) : "r"(addr));
}
// f16 MMA with f16 accumulators: D,C are 2 x b32 (half2-packed)
__device__ __forceinline__ void mma_f16acc(uint32_t* c, const uint32_t* a,
                                           uint32_t b0, uint32_t b1) {
    asm volatile(
        "mma.sync.aligned.m16n8k16.row.col.f16.f16.f16.f16 "
        "{%0,%1}, {%2,%3,%4,%5}, {%6,%7}, {%0,%1};"
        : "+r"(c[0]), "+r"(c[1])
        : "r"(a[0]), "r"(a[1]), "r"(a[2]), "r"(a[3]), "r"(b0), "r"(b1));
}

// ---------------- prep: fp32->f16 (8 floats/iter, 16B stores) + labels ----------------
__device__ __forceinline__ uint4 cvt8(float4 a, float4 b) {
    __half2 h0 = __floats2half2_rn(a.x, a.y);
    __half2 h1 = __floats2half2_rn(a.z, a.w);
    __half2 h2 = __floats2half2_rn(b.x, b.y);
    __half2 h3 = __floats2half2_rn(b.z, b.w);
    uint4 r;
    r.x = *(uint32_t*)&h0; r.y = *(uint32_t*)&h1;
    r.z = *(uint32_t*)&h2; r.w = *(uint32_t*)&h3;
    return r;
}

__global__ void prep_kernel(const float* __restrict__ x, const float* __restrict__ W,
                            const int* __restrict__ yraw) {
    const long long NX8 = (long long)NROWS * CDIM / 8;   // uint4 outputs for x
    const long long NW8 = (long long)VDIM * CDIM / 8;    // uint4 outputs for W
    long long stride = (long long)gridDim.x * blockDim.x;
    long long gid0 = (long long)blockIdx.x * blockDim.x + threadIdx.x;

    const float4* x4 = (const float4*)x;
    const float4* w4 = (const float4*)W;
    for (long long i = gid0; i < NX8; i += stride)
        g_xh[i] = cvt8(x4[2 * i], x4[2 * i + 1]);
    for (long long j = gid0; j < NW8; j += stride)
        g_wh[j] = cvt8(w4[2 * j], w4[2 * j + 1]);

    int gid = blockIdx.x * blockDim.x + threadIdx.x;
    if (gid < NROWS) {
        // int64 labels (values < 2^31, little-endian) -> every odd int32 word is 0
        bool is64 = true;
        #pragma unroll 1
        for (int j = 1; j < 64; j += 2) {
            if (yraw[j] != 0) { is64 = false; break; }
        }
        g_labels[gid] = is64 ? yraw[2 * gid] : yraw[gid];
    }
}

// ---------------- chunk loader: A(128x64) + B/W(128x64) f16, SW128 ----------------
__device__ __forceinline__ void load_chunk(int g, uint32_t smem_base, int t0, int mbase) {
    int vt = g >> 5;               // g / NKC
    int k  = g & (NKC - 1);
    int v0 = (t0 + vt) * VT;
    uint32_t sA = smem_base + SM_STAGE + (uint32_t)(g % 3) * STAGE_SZ;
    uint32_t sB = sA + 16384;
    const char* xb = (const char*)g_xh;
    const char* wb = (const char*)g_wh;
    int tid = threadIdx.x;
    #pragma unroll
    for (int j = 0; j < 4; j++) {            // A: 1024 x 16B
        int o = tid + j * 256;
        int r = o >> 3, c = o & 7;
        const void* src = xb + ((size_t)(mbase + r) * CDIM + (size_t)k * KC) * 2 + c * 16;
        cpa16(sA + sw128((uint32_t)(r * 128 + c * 16)), src);
    }
    #pragma unroll
    for (int j = 0; j < 4; j++) {            // B: 1024 x 16B
        int o = tid + j * 256;
        int r = o >> 3, c = o & 7;
        int vr = v0 + r;
        if (vr >= VDIM) vr = 0;              // dummy row; masked in epilogue
        const void* src = wb + ((size_t)vr * CDIM + (size_t)k * KC) * 2 + c * 16;
        cpa16(sB + sw128((uint32_t)(r * 128 + c * 16)), src);
    }
}

// ---------------- fragment loader (one k-step = k16 f16 = 32B) ----------------
__device__ __forceinline__ void load_frags(uint32_t sA, uint32_t sB,
                                           uint32_t arow0, uint32_t brow0, uint32_t hi16,
                                           int ks, uint32_t a[4][4], uint32_t b[2][4]) {
    #pragma unroll
    for (int mf = 0; mf < 4; mf++) {
        uint32_t off = (arow0 + mf * 16) * 128 + (uint32_t)ks * 32 + hi16;
        ldsm4(a[mf][0], a[mf][1], a[mf][2], a[mf][3], sA + sw128(off));
    }
    #pragma unroll
    for (int p = 0; p < 2; p++) {
        uint32_t off = (brow0 + p * 16) * 128 + (uint32_t)ks * 32 + hi16;
        ldsm4(b[p][0], b[p][1], b[p][2], b[p][3], sB + sw128(off));
    }
}

// ---------------- main fused GEMM + softmax-partial (occ = 2) ----------------
__global__ void __launch_bounds__(256, 2) lce_main(const float* __restrict__ bias) {
    extern __shared__ char smem[];
    uint32_t smem_base = s2u(smem);
    int tid  = threadIdx.x;
    int lane = tid & 31;
    int wm   = (tid >> 5) & 1;      // warp M index (0..1)  -> 64 rows each
    int wn   = tid >> 6;            // warp N index (0..3)  -> 32 cols each

    int split = blockIdx.x >> 6;
    int mb    = blockIdx.x & 63;
    int mbase = mb * MB;
    int t0    = split * TPS;

    int*   s_labels = (int*)(smem + SM_LABELS);
    float* s_rowsum = (float*)(smem + SM_ROWSUM);
    if (tid < 128) {
        s_labels[tid] = g_labels[mbase + tid];
        s_rowsum[tid] = 0.0f;
    }
    __syncthreads();

    // f16-accumulators: [mf][nf][h], each reg = half2 {c0,c1}; 32 regs
    uint32_t acc[4][4][2];
    #pragma unroll
    for (int mf = 0; mf < 4; mf++)
        #pragma unroll
        for (int nf = 0; nf < 4; nf++) {
            acc[mf][nf][0] = 0u; acc[mf][nf][1] = 0u;
        }

    const int total = TPS * NKC;   // 96
    load_chunk(0, smem_base, t0, mbase); cp_commit();
    load_chunk(1, smem_base, t0, mbase); cp_commit();

    const uint32_t arow0 = (uint32_t)(wm * 64 + (lane & 15));
    const uint32_t brow0 = (uint32_t)(wn * 32 + (lane & 15));
    const uint32_t hi16  = (uint32_t)((lane >> 4) * 16);

    uint32_t af[2][4][4], bf[2][2][4];

    for (int g = 0; g < total; g++) {
        // 3-stage / 2-chunk-prologue: at most chunk g+1 outstanding when
        // chunk g is required -> wait until <=1 pending.
        if (g + 1 < total) cp_wait<1>();
        else               cp_wait<0>();
        __syncthreads();
        if (g + 2 < total) { load_chunk(g + 2, smem_base, t0, mbase); cp_commit(); }

        uint32_t sA = smem_base + SM_STAGE + (uint32_t)(g % 3) * STAGE_SZ;
        uint32_t sB = sA + 16384;

        load_frags(sA, sB, arow0, brow0, hi16, 0, af[0], bf[0]);
        #pragma unroll
        for (int ks = 0; ks < 4; ks++) {
            if (ks < 3)
                load_frags(sA, sB, arow0, brow0, hi16, ks + 1,
                           af[(ks + 1) & 1], bf[(ks + 1) & 1]);
            uint32_t (*a)[4] = af[ks & 1];
            uint32_t (*b)[4] = bf[ks & 1];
            #pragma unroll
            for (int mf = 0; mf < 4; mf++)
                #pragma unroll
                for (int nf = 0; nf < 4; nf++) {
                    int p = nf >> 1;
                    uint32_t b0 = (nf & 1) ? b[p][1] : b[p][0];
                    uint32_t b1 = (nf & 1) ? b[p][3] : b[p][2];
                    mma_f16acc(acc[mf][nf], a[mf], b0, b1);
                }
        }

        // epilogue at end of each v-tile: consume register accumulators
        if ((g & (NKC - 1)) == (NKC - 1)) {
            int vt = g >> 5;
            int v0 = (t0 + vt) * VT;
            int colb = v0 + wn * 32 + (lane & 3) * 2;

            float bb[4][2];
            #pragma unroll
            for (int nf = 0; nf < 4; nf++)
                #pragma unroll
                for (int c = 0; c < 2; c++) {
                    int vc = colb + nf * 8 + c;
                    bb[nf][c] = (vc < VDIM) ? bias[vc] : 0.0f;
                }

            int rbase = wm * 64 + (lane >> 2);
            #pragma unroll
            for (int mf = 0; mf < 4; mf++) {
                #pragma unroll
                for (int h = 0; h < 2; h++) {
                    int rl = rbase + mf * 16 + h * 8;
                    int lab = s_labels[rl];
                    float part = 0.0f;
                    #pragma unroll
                    for (int nf = 0; nf < 4; nf++) {
                        float2 dv = __half22float2(*(__half2*)&acc[mf][nf][h]);
                        float lg0 = dv.x + bb[nf][0];
                        float lg1 = dv.y + bb[nf][1];
                        int vc0 = colb + nf * 8;
                        int vc1 = vc0 + 1;
                        if (vc0 < VDIM) {
                            part += ex2f(lg0 * LOG2E);
                            if (vc0 == lab) g_lab[mbase + rl] = lg0;
                        }
                        if (vc1 < VDIM) {
                            part += ex2f(lg1 * LOG2E);
                            if (vc1 == lab) g_lab[mbase + rl] = lg1;
                        }
                        acc[mf][nf][h] = 0u;
                    }
                    part += __shfl_xor_sync(0xFFFFFFFFu, part, 1);
                    part += __shfl_xor_sync(0xFFFFFFFFu, part, 2);
                    if ((lane & 3) == 0) atomicAdd(&s_rowsum[rl], part);
                }
            }

            // flush this vtile's row sums (unique writer per (vt, mb))
            __syncthreads();
            if (tid < 128) {
                g_psum[(size_t)(t0 + vt) * NROWS + mbase + tid] = s_rowsum[tid];
                s_rowsum[tid] = 0.0f;
            }
        }
    }
}

// ---------------- merged final reduce (single block, deterministic) ----------------
__global__ void __launch_bounds__(1024, 1) lce_reduce(float* __restrict__ out) {
    __shared__ float red[1024];
    int tid = threadIdx.x;
    float acc = 0.0f;
    #pragma unroll
    for (int j = 0; j < NROWS / 1024; j++) {
        int row = tid + j * 1024;
        float s = 0.0f;
        #pragma unroll 1
        for (int vt = 0; vt < NVT; vt++) s += g_psum[(size_t)vt * NROWS + row];
        acc += logf(s) - g_lab[row];
    }
    red[tid] = acc;
    __syncthreads();
    for (int off = 512; off > 0; off >>= 1) {
        if (tid < off) red[tid] += red[tid + off];
        __syncthreads();
    }
    if (tid == 0) out[0] = red[0] / (float)NROWS;
}

// ---------------- launch ----------------
extern "C" void kernel_launch(void* const* d_in, const int* in_sizes, int n_in,
                              void* d_out, int out_size) {
    const float* x = nullptr; const float* W = nullptr; const float* b = nullptr;
    const int* y = nullptr;
    for (int i = 0; i < n_in; i++) {
        long long s = in_sizes[i];
        if (s == (long long)NROWS * CDIM)      x = (const float*)d_in[i];
        else if (s == (long long)VDIM * CDIM)  W = (const float*)d_in[i];
        else if (s == VDIM)                    b = (const float*)d_in[i];
        else if (s == NROWS)                   y = (const int*)d_in[i];
    }
    float* out = (float*)d_out;

    cudaFuncSetAttribute(lce_main, cudaFuncAttributeMaxDynamicSharedMemorySize, SMEM_TOTAL);

    prep_kernel<<<4736, 256>>>(x, W, y);
    lce_main<<<GRID_MAIN, 256, SMEM_TOTAL>>>(b);
    lce_reduce<<<1, 1024>>>(out);
}

// round 15
// speedup vs baseline: 1.2422x; 1.2422x over previous
#include <cuda_runtime.h>
#include <cuda_fp16.h>
#include <cstdint>
#include <cfloat>
#include <math.h>

// ---------------- problem constants ----------------
#define NROWS   8192          // B*S
#define CDIM    2048
#define VDIM    50257
#define VT      128           // v-tile width (CTA N)
#define NVT     393           // ceil(VDIM/128)
#define KC      64            // K elems per chunk (128B f16 rows)
#define NKC     (CDIM / KC)   // 32 chunks per v-tile
#define MB      128           // rows per CTA (M)
#define NMB     (NROWS / MB)  // 64
#define TPS     3             // v-tiles per split; 131*3 = 393 exactly
#define NSPLIT  131
#define GRID_MAIN (NSPLIT * NMB)   // 8384
#define LOG2E   1.4426950408889634f

// ---------------- smem layout ----------------
#define STAGES     3
#define STAGE_SZ   32768      // A 128x128B (16KB) + B 128x128B (16KB)
#define SM_LABELS  0          // 128 ints
#define SM_ROWSUM  512        // 128 floats
#define SM_STAGE   1024
#define SMEM_TOTAL (SM_STAGE + STAGES * STAGE_SZ)   // 99328 -> 2 CTAs/SM

// ---------------- device scratch ----------------
__device__ uint4 g_xh[(size_t)NROWS * CDIM / 8];   // x as f16
__device__ uint4 g_wh[(size_t)VDIM * CDIM / 8];    // W as f16
__device__ float g_psum[(size_t)NVT * NROWS];      // per-(vtile,row) partials
__device__ float g_lab[NROWS];
__device__ float g_rowloss[NROWS];
__device__ int   g_labels[NROWS];

// ---------------- helpers ----------------
__device__ __forceinline__ uint32_t s2u(const void* p) {
    uint32_t a;
    asm("{ .reg .u64 t; cvta.to.shared.u64 t, %1; cvt.u32.u64 %0, t; }" : "=r"(a) : "l"(p));
    return a;
}
__device__ __forceinline__ float ex2f(float x) {
    float y; asm("ex2.approx.ftz.f32 %0, %1;" : "=f"(y) : "f"(x)); return y;
}
__device__ __forceinline__ void cpa16(uint32_t dst, const void* src) {
    asm volatile("cp.async.cg.shared.global [%0], [%1], 16;" :: "r"(dst), "l"(src) : "memory");
}
__device__ __forceinline__ void cp_commit() {
    asm volatile("cp.async.commit_group;" ::: "memory");
}
template <int N>
__device__ __forceinline__ void cp_wait() {
    asm volatile("cp.async.wait_group %0;" :: "n"(N) : "memory");
}
__device__ __forceinline__ uint32_t sw128(uint32_t off) { return off ^ ((off >> 3) & 0x70); }

__device__ __forceinline__ void ldsm4(uint32_t& r0, uint32_t& r1, uint32_t& r2, uint32_t& r3,
                                      uint32_t addr) {
    asm volatile("ldmatrix.sync.aligned.m8n8.x4.shared.b16 {%0,%1,%2,%3}, [%4];"
                 : "=r"(r0), "=r"(r1), "=r"(r2), "=r"(r3) : "r"(addr));
}
// f16 MMA with f16 accumulators: D,C are 2 x b32 (half2-packed)
__device__ __forceinline__ void mma_f16acc(uint32_t* c, const uint32_t* a,
                                           uint32_t b0, uint32_t b1) {
    asm volatile(
        "mma.sync.aligned.m16n8k16.row.col.f16.f16.f16.f16 "
        "{%0,%1}, {%2,%3,%4,%5}, {%6,%7}, {%0,%1};"
        : "+r"(c[0]), "+r"(c[1])
        : "r"(a[0]), "r"(a[1]), "r"(a[2]), "r"(a[3]), "r"(b0), "r"(b1));
}

// ---------------- prep: fp32->f16 (8 floats/iter, 16B stores) + labels ----------------
__device__ __forceinline__ uint4 cvt8(float4 a, float4 b) {
    __half2 h0 = __floats2half2_rn(a.x, a.y);
    __half2 h1 = __floats2half2_rn(a.z, a.w);
    __half2 h2 = __floats2half2_rn(b.x, b.y);
    __half2 h3 = __floats2half2_rn(b.z, b.w);
    uint4 r;
    r.x = *(uint32_t*)&h0; r.y = *(uint32_t*)&h1;
    r.z = *(uint32_t*)&h2; r.w = *(uint32_t*)&h3;
    return r;
}

__global__ void prep_kernel(const float* __restrict__ x, const float* __restrict__ W,
                            const int* __restrict__ yraw) {
    const long long NX8 = (long long)NROWS * CDIM / 8;   // uint4 outputs for x
    const long long NW8 = (long long)VDIM * CDIM / 8;    // uint4 outputs for W
    long long stride = (long long)gridDim.x * blockDim.x;
    long long gid0 = (long long)blockIdx.x * blockDim.x + threadIdx.x;

    const float4* x4 = (const float4*)x;
    const float4* w4 = (const float4*)W;
    for (long long i = gid0; i < NX8; i += stride)
        g_xh[i] = cvt8(x4[2 * i], x4[2 * i + 1]);
    for (long long j = gid0; j < NW8; j += stride)
        g_wh[j] = cvt8(w4[2 * j], w4[2 * j + 1]);

    int gid = blockIdx.x * blockDim.x + threadIdx.x;
    if (gid < NROWS) {
        // int64 labels (values < 2^31, little-endian) -> every odd int32 word is 0
        bool is64 = true;
        #pragma unroll 1
        for (int j = 1; j < 64; j += 2) {
            if (yraw[j] != 0) { is64 = false; break; }
        }
        g_labels[gid] = is64 ? yraw[2 * gid] : yraw[gid];
    }
}

// ---------------- chunk loader: A(128x64) + B/W(128x64) f16, SW128 ----------------
__device__ __forceinline__ void load_chunk(int g, uint32_t smem_base, int t0, int mbase) {
    int vt = g >> 5;               // g / NKC
    int k  = g & (NKC - 1);
    int v0 = (t0 + vt) * VT;
    uint32_t sA = smem_base + SM_STAGE + (uint32_t)(g % 3) * STAGE_SZ;
    uint32_t sB = sA + 16384;
    const char* xb = (const char*)g_xh;
    const char* wb = (const char*)g_wh;
    int tid = threadIdx.x;
    #pragma unroll
    for (int j = 0; j < 4; j++) {            // A: 1024 x 16B
        int o = tid + j * 256;
        int r = o >> 3, c = o & 7;
        const void* src = xb + ((size_t)(mbase + r) * CDIM + (size_t)k * KC) * 2 + c * 16;
        cpa16(sA + sw128((uint32_t)(r * 128 + c * 16)), src);
    }
    #pragma unroll
    for (int j = 0; j < 4; j++) {            // B: 1024 x 16B
        int o = tid + j * 256;
        int r = o >> 3, c = o & 7;
        int vr = v0 + r;
        if (vr >= VDIM) vr = 0;              // dummy row; masked in epilogue
        const void* src = wb + ((size_t)vr * CDIM + (size_t)k * KC) * 2 + c * 16;
        cpa16(sB + sw128((uint32_t)(r * 128 + c * 16)), src);
    }
}

// ---------------- fragment loader (one k-step = k16 f16 = 32B) ----------------
__device__ __forceinline__ void load_frags(uint32_t sA, uint32_t sB,
                                           uint32_t arow0, uint32_t brow0, uint32_t hi16,
                                           int ks, uint32_t a[4][4], uint32_t b[2][4]) {
    #pragma unroll
    for (int mf = 0; mf < 4; mf++) {
        uint32_t off = (arow0 + mf * 16) * 128 + (uint32_t)ks * 32 + hi16;
        ldsm4(a[mf][0], a[mf][1], a[mf][2], a[mf][3], sA + sw128(off));
    }
    #pragma unroll
    for (int p = 0; p < 2; p++) {
        uint32_t off = (brow0 + p * 16) * 128 + (uint32_t)ks * 32 + hi16;
        ldsm4(b[p][0], b[p][1], b[p][2], b[p][3], sB + sw128(off));
    }
}

// ---------------- main fused GEMM + softmax-partial (occ = 2) ----------------
__global__ void __launch_bounds__(256, 2) lce_main(const float* __restrict__ bias) {
    extern __shared__ char smem[];
    uint32_t smem_base = s2u(smem);
    int tid  = threadIdx.x;
    int lane = tid & 31;
    int wm   = (tid >> 5) & 1;      // warp M index (0..1)  -> 64 rows each
    int wn   = tid >> 6;            // warp N index (0..3)  -> 32 cols each

    int split = blockIdx.x >> 6;
    int mb    = blockIdx.x & 63;
    int mbase = mb * MB;
    int t0    = split * TPS;

    int*   s_labels = (int*)(smem + SM_LABELS);
    float* s_rowsum = (float*)(smem + SM_ROWSUM);
    if (tid < 128) {
        s_labels[tid] = g_labels[mbase + tid];
        s_rowsum[tid] = 0.0f;
    }
    __syncthreads();

    // f16-accumulators: [mf][nf][h], each reg = half2 {c0,c1}; 32 regs
    uint32_t acc[4][4][2];
    #pragma unroll
    for (int mf = 0; mf < 4; mf++)
        #pragma unroll
        for (int nf = 0; nf < 4; nf++) {
            acc[mf][nf][0] = 0u; acc[mf][nf][1] = 0u;
        }

    const int total = TPS * NKC;   // 96
    load_chunk(0, smem_base, t0, mbase); cp_commit();
    load_chunk(1, smem_base, t0, mbase); cp_commit();

    const uint32_t arow0 = (uint32_t)(wm * 64 + (lane & 15));
    const uint32_t brow0 = (uint32_t)(wn * 32 + (lane & 15));
    const uint32_t hi16  = (uint32_t)((lane >> 4) * 16);

    uint32_t af[2][4][4], bf[2][2][4];

    for (int g = 0; g < total; g++) {
        // 3-stage / 2-chunk-prologue: at most chunk g+1 outstanding when
        // chunk g is required -> wait until <=1 pending.
        if (g + 1 < total) cp_wait<1>();
        else               cp_wait<0>();
        __syncthreads();
        if (g + 2 < total) { load_chunk(g + 2, smem_base, t0, mbase); cp_commit(); }

        uint32_t sA = smem_base + SM_STAGE + (uint32_t)(g % 3) * STAGE_SZ;
        uint32_t sB = sA + 16384;

        load_frags(sA, sB, arow0, brow0, hi16, 0, af[0], bf[0]);
        #pragma unroll
        for (int ks = 0; ks < 4; ks++) {
            if (ks < 3)
                load_frags(sA, sB, arow0, brow0, hi16, ks + 1,
                           af[(ks + 1) & 1], bf[(ks + 1) & 1]);
            uint32_t (*a)[4] = af[ks & 1];
            uint32_t (*b)[4] = bf[ks & 1];
            #pragma unroll
            for (int mf = 0; mf < 4; mf++)
                #pragma unroll
                for (int nf = 0; nf < 4; nf++) {
                    int p = nf >> 1;
                    uint32_t b0 = (nf & 1) ? b[p][1] : b[p][0];
                    uint32_t b1 = (nf & 1) ? b[p][3] : b[p][2];
                    mma_f16acc(acc[mf][nf], a[mf], b0, b1);
                }
        }

        // epilogue at end of each v-tile: consume register accumulators
        if ((g & (NKC - 1)) == (NKC - 1)) {
            int vt = g >> 5;
            int v0 = (t0 + vt) * VT;
            int colb = v0 + wn * 32 + (lane & 3) * 2;

            float bb[4][2];
            #pragma unroll
            for (int nf = 0; nf < 4; nf++)
                #pragma unroll
                for (int c = 0; c < 2; c++) {
                    int vc = colb + nf * 8 + c;
                    bb[nf][c] = (vc < VDIM) ? bias[vc] : 0.0f;
                }

            int rbase = wm * 64 + (lane >> 2);
            #pragma unroll
            for (int mf = 0; mf < 4; mf++) {
                #pragma unroll
                for (int h = 0; h < 2; h++) {
                    int rl = rbase + mf * 16 + h * 8;
                    int lab = s_labels[rl];
                    float part = 0.0f;
                    #pragma unroll
                    for (int nf = 0; nf < 4; nf++) {
                        float2 dv = __half22float2(*(__half2*)&acc[mf][nf][h]);
                        float lg0 = dv.x + bb[nf][0];
                        float lg1 = dv.y + bb[nf][1];
                        int vc0 = colb + nf * 8;
                        int vc1 = vc0 + 1;
                        if (vc0 < VDIM) {
                            part += ex2f(lg0 * LOG2E);
                            if (vc0 == lab) g_lab[mbase + rl] = lg0;
                        }
                        if (vc1 < VDIM) {
                            part += ex2f(lg1 * LOG2E);
                            if (vc1 == lab) g_lab[mbase + rl] = lg1;
                        }
                        acc[mf][nf][h] = 0u;
                    }
                    part += __shfl_xor_sync(0xFFFFFFFFu, part, 1);
                    part += __shfl_xor_sync(0xFFFFFFFFu, part, 2);
                    if ((lane & 3) == 0) atomicAdd(&s_rowsum[rl], part);
                }
            }

            // flush this vtile's row sums (unique writer per (vt, mb))
            __syncthreads();
            if (tid < 128) {
                g_psum[(size_t)(t0 + vt) * NROWS + mbase + tid] = s_rowsum[tid];
                s_rowsum[tid] = 0.0f;
            }
        }
    }
}

// ---------------- reduction stage 1: per-row loss (parallel, deterministic) ----------------
__global__ void __launch_bounds__(256, 1) lce_rowloss() {
    int row = blockIdx.x * blockDim.x + threadIdx.x;
    if (row >= NROWS) return;
    float s = 0.0f;
    #pragma unroll 1
    for (int vt = 0; vt < NVT; vt++) s += g_psum[(size_t)vt * NROWS + row];
    g_rowloss[row] = logf(s) - g_lab[row];
}

// ---------------- reduction stage 2: deterministic tree over 8192 ----------------
__global__ void __launch_bounds__(1024, 1) lce_reduce(float* __restrict__ out) {
    __shared__ float red[1024];
    int tid = threadIdx.x;
    float acc = 0.0f;
    #pragma unroll
    for (int j = 0; j < NROWS / 1024; j++) acc += g_rowloss[tid + j * 1024];
    red[tid] = acc;
    __syncthreads();
    for (int off = 512; off > 0; off >>= 1) {
        if (tid < off) red[tid] += red[tid + off];
        __syncthreads();
    }
    if (tid == 0) out[0] = red[0] / (float)NROWS;
}

// ---------------- launch ----------------
extern "C" void kernel_launch(void* const* d_in, const int* in_sizes, int n_in,
                              void* d_out, int out_size) {
    const float* x = nullptr; const float* W = nullptr; const float* b = nullptr;
    const int* y = nullptr;
    for (int i = 0; i < n_in; i++) {
        long long s = in_sizes[i];
        if (s == (long long)NROWS * CDIM)      x = (const float*)d_in[i];
        else if (s == (long long)VDIM * CDIM)  W = (const float*)d_in[i];
        else if (s == VDIM)                    b = (const float*)d_in[i];
        else if (s == NROWS)                   y = (const int*)d_in[i];
    }
    float* out = (float*)d_out;

    cudaFuncSetAttribute(lce_main, cudaFuncAttributeMaxDynamicSharedMemorySize, SMEM_TOTAL);

    prep_kernel<<<4736, 256>>>(x, W, y);
    lce_main<<<GRID_MAIN, 256, SMEM_TOTAL>>>(b);
    lce_rowloss<<<NROWS / 256, 256>>>();
    lce_reduce<<<1, 1024>>>(out);
}

// round 16
// speedup vs baseline: 1.4066x; 1.1324x over previous
#include <cuda_runtime.h>
#include <cuda_fp16.h>
#include <cstdint>
#include <cfloat>
#include <math.h>

// ---------------- problem constants ----------------
#define NROWS   8192          // B*S
#define CDIM    2048
#define VDIM    50257
#define VT      256           // v-tile width (CTA N)
#define NVT     197           // ceil(VDIM/256)
#define KC      64            // K elems per chunk (128B f16 rows)
#define NKC     (CDIM / KC)   // 32 chunks per v-tile
#define MB      128           // rows per CTA (M)
#define NMB     (NROWS / MB)  // 64
#define GRID_MAIN (NVT * NMB) // 12608 (one vtile per CTA; vt-major for W sharing)
#define LOG2E   1.4426950408889634f

// ---------------- smem layout ----------------
#define STAGES     2
#define STAGE_SZ   49152      // A 128x128B (16KB) + B 256x128B (32KB)
#define SM_LABELS  0          // 128 ints
#define SM_ROWSUM  512        // 128 floats
#define SM_STAGE   1024
#define SMEM_TOTAL (SM_STAGE + STAGES * STAGE_SZ)   // 99328 -> 2 CTAs/SM

// ---------------- device scratch ----------------
__device__ uint4 g_xh[(size_t)NROWS * CDIM / 8];   // x as f16
__device__ uint4 g_wh[(size_t)VDIM * CDIM / 8];    // W as f16
__device__ float g_psum[(size_t)NVT * NROWS];      // per-(vtile,row) partials
__device__ float g_lab[NROWS];
__device__ float g_rowloss[NROWS];
__device__ int   g_labels[NROWS];

// ---------------- helpers ----------------
__device__ __forceinline__ uint32_t s2u(const void* p) {
    uint32_t a;
    asm("{ .reg .u64 t; cvta.to.shared.u64 t, %1; cvt.u32.u64 %0, t; }" : "=r"(a) : "l"(p));
    return a;
}
__device__ __forceinline__ float ex2f(float x) {
    float y; asm("ex2.approx.ftz.f32 %0, %1;" : "=f"(y) : "f"(x)); return y;
}
__device__ __forceinline__ void cpa16(uint32_t dst, const void* src) {
    asm volatile("cp.async.cg.shared.global [%0], [%1], 16;" :: "r"(dst), "l"(src) : "memory");
}
__device__ __forceinline__ void cp_commit() {
    asm volatile("cp.async.commit_group;" ::: "memory");
}
template <int N>
__device__ __forceinline__ void cp_wait() {
    asm volatile("cp.async.wait_group %0;" :: "n"(N) : "memory");
}
__device__ __forceinline__ uint32_t sw128(uint32_t off) { return off ^ ((off >> 3) & 0x70); }

__device__ __forceinline__ void ldsm4(uint32_t& r0, uint32_t& r1, uint32_t& r2, uint32_t& r3,
                                      uint32_t addr) {
    asm volatile("ldmatrix.sync.aligned.m8n8.x4.shared.b16 {%0,%1,%2,%3}, [%4];"
                 : "=r"(r0), "=r"(r1), "=r"(r2), "=r"(r3) : "r"(addr));
}
// f16 MMA with f16 accumulators: D,C are 2 x b32 (half2-packed)
__device__ __forceinline__ void mma_f16acc(uint32_t* c, const uint32_t* a,
                                           uint32_t b0, uint32_t b1) {
    asm volatile(
        "mma.sync.aligned.m16n8k16.row.col.f16.f16.f16.f16 "
        "{%0,%1}, {%2,%3,%4,%5}, {%6,%7}, {%0,%1};"
        : "+r"(c[0]), "+r"(c[1])
        : "r"(a[0]), "r"(a[1]), "r"(a[2]), "r"(a[3]), "r"(b0), "r"(b1));
}

// ---------------- prep: fp32->f16 (8 floats/iter, 16B stores) + labels ----------------
__device__ __forceinline__ uint4 cvt8(float4 a, float4 b) {
    __half2 h0 = __floats2half2_rn(a.x, a.y);
    __half2 h1 = __floats2half2_rn(a.z, a.w);
    __half2 h2 = __floats2half2_rn(b.x, b.y);
    __half2 h3 = __floats2half2_rn(b.z, b.w);
    uint4 r;
    r.x = *(uint32_t*)&h0; r.y = *(uint32_t*)&h1;
    r.z = *(uint32_t*)&h2; r.w = *(uint32_t*)&h3;
    return r;
}

__global__ void prep_kernel(const float* __restrict__ x, const float* __restrict__ W,
                            const int* __restrict__ yraw) {
    const long long NX8 = (long long)NROWS * CDIM / 8;
    const long long NW8 = (long long)VDIM * CDIM / 8;
    long long stride = (long long)gridDim.x * blockDim.x;
    long long gid0 = (long long)blockIdx.x * blockDim.x + threadIdx.x;

    const float4* x4 = (const float4*)x;
    const float4* w4 = (const float4*)W;
    for (long long i = gid0; i < NX8; i += stride)
        g_xh[i] = cvt8(x4[2 * i], x4[2 * i + 1]);
    for (long long j = gid0; j < NW8; j += stride)
        g_wh[j] = cvt8(w4[2 * j], w4[2 * j + 1]);

    int gid = blockIdx.x * blockDim.x + threadIdx.x;
    if (gid < NROWS) {
        // int64 labels (values < 2^31, little-endian) -> every odd int32 word is 0
        bool is64 = true;
        #pragma unroll 1
        for (int j = 1; j < 64; j += 2) {
            if (yraw[j] != 0) { is64 = false; break; }
        }
        g_labels[gid] = is64 ? yraw[2 * gid] : yraw[gid];
    }
}

// ---------------- chunk loader: A(128x64) + B/W(256x64) f16, SW128 ----------------
__device__ __forceinline__ void load_chunk(int k, uint32_t smem_base, int v0, int mbase) {
    uint32_t sA = smem_base + SM_STAGE + (uint32_t)(k & 1) * STAGE_SZ;
    uint32_t sB = sA + 16384;
    const char* xb = (const char*)g_xh;
    const char* wb = (const char*)g_wh;
    int tid = threadIdx.x;
    #pragma unroll
    for (int j = 0; j < 4; j++) {            // A: 1024 x 16B
        int o = tid + j * 256;
        int r = o >> 3, c = o & 7;
        const void* src = xb + ((size_t)(mbase + r) * CDIM + (size_t)k * KC) * 2 + c * 16;
        cpa16(sA + sw128((uint32_t)(r * 128 + c * 16)), src);
    }
    #pragma unroll
    for (int j = 0; j < 8; j++) {            // B: 2048 x 16B
        int o = tid + j * 256;
        int r = o >> 3, c = o & 7;
        int vr = v0 + r;
        if (vr >= VDIM) vr = 0;              // dummy row; masked in epilogue
        const void* src = wb + ((size_t)vr * CDIM + (size_t)k * KC) * 2 + c * 16;
        cpa16(sB + sw128((uint32_t)(r * 128 + c * 16)), src);
    }
}

// ---------------- main fused GEMM + softmax-partial (VT=256, occ=2, 2 stages) ----------------
__global__ void __launch_bounds__(256, 2) lce_main(const float* __restrict__ bias) {
    extern __shared__ char smem[];
    uint32_t smem_base = s2u(smem);
    int tid  = threadIdx.x;
    int lane = tid & 31;
    int wm   = (tid >> 5) & 1;      // warp M index (0..1)  -> 64 rows each
    int wn   = tid >> 6;            // warp N index (0..3)  -> 64 cols each

    int vt    = blockIdx.x >> 6;    // vt-major: 64 consecutive CTAs share this W vtile
    int mb    = blockIdx.x & 63;
    int mbase = mb * MB;
    int v0    = vt * VT;

    int*   s_labels = (int*)(smem + SM_LABELS);
    float* s_rowsum = (float*)(smem + SM_ROWSUM);
    if (tid < 128) {
        s_labels[tid] = g_labels[mbase + tid];
        s_rowsum[tid] = 0.0f;
    }
    __syncthreads();

    // f16-accumulators: [mf][nf][h], each reg = half2 {c0,c1}; 64 regs
    uint32_t acc[4][8][2];
    #pragma unroll
    for (int mf = 0; mf < 4; mf++)
        #pragma unroll
        for (int nf = 0; nf < 8; nf++) {
            acc[mf][nf][0] = 0u; acc[mf][nf][1] = 0u;
        }

    load_chunk(0, smem_base, v0, mbase); cp_commit();

    const uint32_t arow0 = (uint32_t)(wm * 64 + (lane & 15));
    const uint32_t brow0 = (uint32_t)(wn * 64 + (lane & 15));
    const uint32_t hi16  = (uint32_t)((lane >> 4) * 16);

    for (int k = 0; k < NKC; k++) {
        cp_wait<0>();               // chunk k ready (issued previous iter / prologue)
        __syncthreads();
        if (k + 1 < NKC) { load_chunk(k + 1, smem_base, v0, mbase); cp_commit(); }

        uint32_t sA = smem_base + SM_STAGE + (uint32_t)(k & 1) * STAGE_SZ;
        uint32_t sB = sA + 16384;

        #pragma unroll
        for (int ks = 0; ks < 4; ks++) {
            uint32_t a[4][4], b[4][4];
            #pragma unroll
            for (int mf = 0; mf < 4; mf++) {
                uint32_t off = (arow0 + mf * 16) * 128 + (uint32_t)ks * 32 + hi16;
                ldsm4(a[mf][0], a[mf][1], a[mf][2], a[mf][3], sA + sw128(off));
            }
            #pragma unroll
            for (int p = 0; p < 4; p++) {
                uint32_t off = (brow0 + p * 16) * 128 + (uint32_t)ks * 32 + hi16;
                ldsm4(b[p][0], b[p][1], b[p][2], b[p][3], sB + sw128(off));
            }
            #pragma unroll
            for (int mf = 0; mf < 4; mf++)
                #pragma unroll
                for (int nf = 0; nf < 8; nf++) {
                    int p = nf >> 1;
                    uint32_t b0 = (nf & 1) ? b[p][1] : b[p][0];
                    uint32_t b1 = (nf & 1) ? b[p][3] : b[p][2];
                    mma_f16acc(acc[mf][nf], a[mf], b0, b1);
                }
        }
        __syncthreads();            // all ldsm done before stage reuse next iter
    }

    // ---------------- epilogue (once per CTA) ----------------
    {
        int colb = v0 + wn * 64 + (lane & 3) * 2;
        float bb[8][2];
        #pragma unroll
        for (int nf = 0; nf < 8; nf++)
            #pragma unroll
            for (int c = 0; c < 2; c++) {
                int vc = colb + nf * 8 + c;
                bb[nf][c] = (vc < VDIM) ? bias[vc] : 0.0f;
            }

        int rbase = wm * 64 + (lane >> 2);
        #pragma unroll
        for (int mf = 0; mf < 4; mf++) {
            #pragma unroll
            for (int h = 0; h < 2; h++) {
                int rl = rbase + mf * 16 + h * 8;
                int lab = s_labels[rl];
                float part = 0.0f;
                #pragma unroll
                for (int nf = 0; nf < 8; nf++) {
                    float2 dv = __half22float2(*(__half2*)&acc[mf][nf][h]);
                    float lg0 = dv.x + bb[nf][0];
                    float lg1 = dv.y + bb[nf][1];
                    int vc0 = colb + nf * 8;
                    int vc1 = vc0 + 1;
                    if (vc0 < VDIM) {
                        part += ex2f(lg0 * LOG2E);
                        if (vc0 == lab) g_lab[mbase + rl] = lg0;
                    }
                    if (vc1 < VDIM) {
                        part += ex2f(lg1 * LOG2E);
                        if (vc1 == lab) g_lab[mbase + rl] = lg1;
                    }
                }
                part += __shfl_xor_sync(0xFFFFFFFFu, part, 1);
                part += __shfl_xor_sync(0xFFFFFFFFu, part, 2);
                if ((lane & 3) == 0) atomicAdd(&s_rowsum[rl], part);
            }
        }

        __syncthreads();
        if (tid < 128)
            g_psum[(size_t)vt * NROWS + mbase + tid] = s_rowsum[tid];
    }
}

// ---------------- reduction stage 1: per-row loss (parallel, deterministic) ----------------
__global__ void __launch_bounds__(256, 1) lce_rowloss() {
    int row = blockIdx.x * blockDim.x + threadIdx.x;
    if (row >= NROWS) return;
    float s = 0.0f;
    #pragma unroll 1
    for (int vt = 0; vt < NVT; vt++) s += g_psum[(size_t)vt * NROWS + row];
    g_rowloss[row] = logf(s) - g_lab[row];
}

// ---------------- reduction stage 2: deterministic tree over 8192 ----------------
__global__ void __launch_bounds__(1024, 1) lce_reduce(float* __restrict__ out) {
    __shared__ float red[1024];
    int tid = threadIdx.x;
    float acc = 0.0f;
    #pragma unroll
    for (int j = 0; j < NROWS / 1024; j++) acc += g_rowloss[tid + j * 1024];
    red[tid] = acc;
    __syncthreads();
    for (int off = 512; off > 0; off >>= 1) {
        if (tid < off) red[tid] += red[tid + off];
        __syncthreads();
    }
    if (tid == 0) out[0] = red[0] / (float)NROWS;
}

// ---------------- launch ----------------
extern "C" void kernel_launch(void* const* d_in, const int* in_sizes, int n_in,
                              void* d_out, int out_size) {
    const float* x = nullptr; const float* W = nullptr; const float* b = nullptr;
    const int* y = nullptr;
    for (int i = 0; i < n_in; i++) {
        long long s = in_sizes[i];
        if (s == (long long)NROWS * CDIM)      x = (const float*)d_in[i];
        else if (s == (long long)VDIM * CDIM)  W = (const float*)d_in[i];
        else if (s == VDIM)                    b = (const float*)d_in[i];
        else if (s == NROWS)                   y = (const int*)d_in[i];
    }
    float* out = (float*)d_out;

    cudaFuncSetAttribute(lce_main, cudaFuncAttributeMaxDynamicSharedMemorySize, SMEM_TOTAL);

    prep_kernel<<<4736, 256>>>(x, W, y);
    lce_main<<<GRID_MAIN, 256, SMEM_TOTAL>>>(b);
    lce_rowloss<<<NROWS / 256, 256>>>();
    lce_reduce<<<1, 1024>>>(out);
}